// round 6
// baseline (speedup 1.0000x reference)
#include <cuda_runtime.h>
#include <cstring>

#define NLAYERS 200
#define KSIZE   7
#define L_IN    1388
#define NPAIR   694        // float2 pairs per row
#define FC_IN   188
#define FC_OUT  91
#define ROWS_PER_CTA 4
#define WARPS_PER_CTA (2 * ROWS_PER_CTA)   // 2 warps per row
#define NT      (32 * WARPS_PER_CTA)       // 256 threads
#define HC      11          // pairs per lane per half-row (32*11 = 352)
#define HALF_P  352         // pairs owned by each warp
#define COOP_LAYERS 114     // layers 0..113 cooperative; then solo fits 352 pairs

// Packed dual-fp32 FMA (Blackwell f32x2).
static __device__ __forceinline__ float2 ffma2(float2 a, float2 b, float2 c) {
    unsigned long long ua, ub, uc, ud;
    memcpy(&ua, &a, 8); memcpy(&ub, &b, 8); memcpy(&uc, &c, 8);
    asm("fma.rn.f32x2 %0, %1, %2, %3;" : "=l"(ud) : "l"(ua), "l"(ub), "l"(uc));
    float2 d; memcpy(&d, &ud, 8);
    return d;
}

static __device__ __forceinline__ float2 shfl_down1_f2(float2 v) {
    float2 r;
    r.x = __shfl_down_sync(0xffffffffu, v.x, 1);
    r.y = __shfl_down_sync(0xffffffffu, v.y, 1);
    return r;
}

// Core conv body at compile-time pair-chunk C, given halo pairs h[0..2].
template<int C>
static __device__ __forceinline__ void conv_body(float2* p, const float2* w,
                                                 float2 b, bool relu, float2* h)
{
    float2 s0 = make_float2(p[0].y, p[1].x);
    float2 s1 = make_float2(p[1].y, p[2].x);
    float2 s2 = make_float2(p[2].y, p[3].x);
    #pragma unroll
    for (int j = 0; j < C; j++) {
        float2 v1 = (j + 1 < C) ? p[j + 1] : h[j + 1 - C];
        float2 v2 = (j + 2 < C) ? p[j + 2] : h[j + 2 - C];
        float2 v3 = (j + 3 < C) ? p[j + 3] : h[j + 3 - C];
        float2 acc = b;
        acc = ffma2(w[0], p[j], acc);
        acc = ffma2(w[1], s0,   acc);
        acc = ffma2(w[2], v1,   acc);
        acc = ffma2(w[3], s1,   acc);
        acc = ffma2(w[4], v2,   acc);
        acc = ffma2(w[5], s2,   acc);
        acc = ffma2(w[6], v3,   acc);
        float2 snext = s2;
        if (j < C - 1) {
            float2 v4 = (j + 4 < C) ? p[j + 4] : h[j + 4 - C];
            snext = make_float2(v3.y, v4.x);
        }
        if (relu) { acc.x = fmaxf(acc.x, 0.0f); acc.y = fmaxf(acc.y, 0.0f); }
        p[j] = acc;
        s0 = s1; s1 = s2; s2 = snext;
    }
}

// Solo phase (warp0 alone): nl layers at chunk C, halo purely via SHFL.
template<int C>
static __device__ __forceinline__ void conv_phase(float2* p, int layer0, int nl,
                                                  const float2* __restrict__ ws2,
                                                  const float2* __restrict__ bs2)
{
    #pragma unroll 1
    for (int i = 0; i < nl; i++) {
        const int L = layer0 + i;
        float2 w[KSIZE];
        #pragma unroll
        for (int k = 0; k < KSIZE; k++) w[k] = ws2[L * KSIZE + k];
        float2 b = bs2[L];
        float2 h[3];
        #pragma unroll
        for (int j = 0; j < 3; j++) h[j] = shfl_down1_f2(p[j]);
        conv_body<C>(p, w, b, (L != NLAYERS - 1), h);
    }
}

template<int CO, int CN, int VIN>
static __device__ __forceinline__ void repack(float2* p, float2* stg, int lane)
{
    __syncwarp();
    #pragma unroll
    for (int c = 0; c < CO; c++) {
        int g = lane * CO + c;
        if (g < VIN) stg[g] = p[c];
    }
    __syncwarp();
    #pragma unroll
    for (int c = 0; c < CN; c++) {
        int g = lane * CN + c;
        p[c] = (g < VIN) ? stg[g] : make_float2(0.0f, 0.0f);
    }
    __syncwarp();
}

__global__ __launch_bounds__(NT, 2)
void conv200_kernel(const float* __restrict__ x,
                    const float* __restrict__ conv_w,
                    const float* __restrict__ conv_b,
                    const float* __restrict__ fc_w,
                    const float* __restrict__ fc_b,
                    float* __restrict__ out)
{
    __shared__ float2 stg_all[WARPS_PER_CTA][HALF_P];   // 22.5 KB (load + repack)
    __shared__ float2 ws2[NLAYERS * KSIZE];             // 11.2 KB packed (w,w)
    __shared__ float2 bs2[NLAYERS];                     // 1.6 KB packed (b,b)
    __shared__ float2 halo_sm[ROWS_PER_CTA][2][4];      // per-pair double-buffered halo

    const int t    = threadIdx.x;
    const int wid  = t >> 5;
    const int lane = t & 31;
    const int pairid = wid >> 1;        // row within CTA
    const int half   = wid & 1;         // 0 = left/owner warp, 1 = right/halo warp

    for (int j = t; j < NLAYERS * KSIZE; j += NT) {
        float w = conv_w[j];
        ws2[j] = make_float2(w, w);
    }
    for (int j = t; j < NLAYERS; j += NT) {
        float b = conv_b[j];
        bs2[j] = make_float2(b, b);
    }
    __syncthreads();

    const int row = blockIdx.x * ROWS_PER_CTA + pairid;
    const float2* xr = reinterpret_cast<const float2*>(x + (size_t)row * L_IN);
    float2* stg = stg_all[wid];

    // coalesced load of this warp's half (pairs [half*352, half*352+352))
    const int pbase = half * HALF_P;
    for (int j = lane; j < HALF_P; j += 32) {
        int g = pbase + j;
        stg[j] = (g < NPAIR) ? __ldg(&xr[g]) : make_float2(0.0f, 0.0f);
    }
    __syncwarp();
    float2 p[HC];
    #pragma unroll
    for (int c = 0; c < HC; c++) p[c] = stg[lane * HC + c];

    // ---- cooperative phase: layers 0..113, one named barrier per layer ----
    const int barid = 1 + pairid;
    float2* hb = &halo_sm[pairid][0][0];
    #pragma unroll 1
    for (int i = 0; i < COOP_LAYERS; i++) {
        float2* buf = hb + (i & 1) * 4;
        if (half == 1 && lane == 0) {   // publish warp1's first 3 input pairs
            buf[0] = p[0]; buf[1] = p[1]; buf[2] = p[2];
        }
        asm volatile("bar.sync %0, %1;" :: "r"(barid), "r"(64) : "memory");

        float2 w[KSIZE];
        #pragma unroll
        for (int k = 0; k < KSIZE; k++) w[k] = ws2[i * KSIZE + k];
        float2 b = bs2[i];
        float2 h[3];
        #pragma unroll
        for (int j = 0; j < 3; j++) h[j] = shfl_down1_f2(p[j]);
        if (half == 0 && lane == 31) { h[0] = buf[0]; h[1] = buf[1]; h[2] = buf[2]; }
        conv_body<HC>(p, w, b, true, h);   // layers < 199 always have ReLU here
    }

    if (half == 0) {
        // ---- solo phase: layers 114..199, valid pairs 352 -> 94 ----
        conv_phase<11>(p, 114, 11, ws2, bs2);
        repack<11, 10, 319>(p, stg, lane); conv_phase<10>(p, 125, 11, ws2, bs2);
        repack<10,  9, 286>(p, stg, lane); conv_phase< 9>(p, 136, 10, ws2, bs2);
        repack< 9,  8, 256>(p, stg, lane); conv_phase< 8>(p, 146, 11, ws2, bs2);
        repack< 8,  7, 223>(p, stg, lane); conv_phase< 7>(p, 157, 11, ws2, bs2);
        repack< 7,  6, 190>(p, stg, lane); conv_phase< 6>(p, 168, 10, ws2, bs2);
        repack< 6,  5, 160>(p, stg, lane); conv_phase< 5>(p, 178, 11, ws2, bs2);
        repack< 5,  4, 127>(p, stg, lane); conv_phase< 4>(p, 189, 11, ws2, bs2);

        // gather final 94 valid pairs (188 elements)
        __syncwarp();
        #pragma unroll
        for (int c = 0; c < 4; c++) {
            int g = lane * 4 + c;
            if (g < FC_IN / 2) stg[g] = p[c];
        }
        __syncwarp();

        // FC 188->91 + sigmoid: lane handles outputs {lane, lane+32, lane+64}
        const float2* fw2 = reinterpret_cast<const float2*>(fc_w);
        float2 acc[3];
        #pragma unroll
        for (int u = 0; u < 3; u++) acc[u] = make_float2(0.0f, 0.0f);
        int o0 = lane, o1 = lane + 32, o2 = lane + 64;
        int c2 = (o2 < FC_OUT) ? o2 : (FC_OUT - 1);
        const float2* r0w = fw2 + (size_t)o0 * (FC_IN / 2);
        const float2* r1w = fw2 + (size_t)o1 * (FC_IN / 2);
        const float2* r2w = fw2 + (size_t)c2 * (FC_IN / 2);
        #pragma unroll 2
        for (int j = 0; j < FC_IN / 2; j++) {
            float2 hv = stg[j];
            acc[0] = ffma2(__ldg(&r0w[j]), hv, acc[0]);
            acc[1] = ffma2(__ldg(&r1w[j]), hv, acc[1]);
            acc[2] = ffma2(__ldg(&r2w[j]), hv, acc[2]);
        }
        float* orow = out + (size_t)row * FC_OUT;
        float s0 = acc[0].x + acc[0].y + __ldg(&fc_b[o0]);
        float s1 = acc[1].x + acc[1].y + __ldg(&fc_b[o1]);
        orow[o0] = 1.0f / (1.0f + __expf(-s0));
        orow[o1] = 1.0f / (1.0f + __expf(-s1));
        if (o2 < FC_OUT) {
            float s2 = acc[2].x + acc[2].y + __ldg(&fc_b[o2]);
            orow[o2] = 1.0f / (1.0f + __expf(-s2));
        }
    }
}

extern "C" void kernel_launch(void* const* d_in, const int* in_sizes, int n_in,
                              void* d_out, int out_size)
{
    const float* x      = (const float*)d_in[0];   // [1024, 1388]
    const float* conv_w = (const float*)d_in[1];   // [200, 7]
    const float* conv_b = (const float*)d_in[2];   // [200]
    const float* fc_w   = (const float*)d_in[3];   // [91, 188]
    const float* fc_b   = (const float*)d_in[4];   // [91]
    float* out          = (float*)d_out;           // [1024, 91]

    const int B = in_sizes[0] / L_IN;              // 1024 rows
    conv200_kernel<<<B / ROWS_PER_CTA, NT>>>(x, conv_w, conv_b, fc_w, fc_b, out);
}